// round 7
// baseline (speedup 1.0000x reference)
#include <cuda_runtime.h>
#include <cstdint>

typedef unsigned long long ull;

// ---------------- problem constants ----------------
#define T_STEPS 2048
#define BATCH   64
#define FEAT    13
#define HID     300
#define OUT_MAIN (BATCH*T_STEPS*FEAT)
#define OUT_EMB_OFF OUT_MAIN

// ---------------- encoder config ----------------
#define CLUSTER 8
#define NB      4               // batch per cluster
#define TENC    480
#define HC      38              // hidden units per CTA (8*38 = 304 >= 300)
#define ROWP    40              // padded rows per gate
#define R3      120
#define KSPLIT  8               // one k-split per source rank chunk
#define KSEG2P  20              // k-pairs per rank chunk (padded: 38 real + 2 zero)
#define RG      60              // row-pairs; 8*60 = 480 threads
#define BSTRIDE (KSEG2P*8)      // 160 B per batch inside a chunk buffer
#define PSTRIDE (NB*KSEG2P*8)   // 640 B per parity buffer

__device__ float g_hlast[BATCH*HID];
__device__ float g_emb[BATCH*HID];

// ---------------- helpers ----------------
__device__ __forceinline__ float sig_f(float x) {
    return __fdividef(1.f, 1.f + __expf(-x));
}
__device__ __forceinline__ float tanh_f(float x) {
    return 1.f - __fdividef(2.f, __expf(2.f * x) + 1.f);
}
__device__ __forceinline__ unsigned smem_u32(const void* p) {
    unsigned a;
    asm("{ .reg .u64 t; cvta.to.shared.u64 t, %1; cvt.u32.u64 %0, t; }"
        : "=r"(a) : "l"(p));
    return a;
}
__device__ __forceinline__ void cluster_sync_() {
    asm volatile("barrier.cluster.arrive.aligned;" ::: "memory");
    asm volatile("barrier.cluster.wait.aligned;" ::: "memory");
}
__device__ __forceinline__ ull pk2(float lo, float hi) {
    ull r;
    asm("mov.b64 %0, {%1, %2};" : "=l"(r) : "f"(lo), "f"(hi));
    return r;
}
__device__ __forceinline__ void fma2(ull& d, ull a, ull b) {
    asm("fma.rn.f32x2 %0, %1, %2, %0;" : "+l"(d) : "l"(a), "l"(b));
}
__device__ __forceinline__ float upks(ull v) {
    float lo, hi;
    asm("mov.b64 {%0, %1}, %2;" : "=f"(lo), "=f"(hi) : "l"(v));
    return lo + hi;
}
__device__ __forceinline__ unsigned mapa_(unsigned a, int rank) {
    unsigned r;
    asm("mapa.shared::cluster.u32 %0, %1, %2;" : "=r"(r) : "r"(a), "r"(rank));
    return r;
}
__device__ __forceinline__ void mbar_init(unsigned a, unsigned cnt) {
    asm volatile("mbarrier.init.shared.b64 [%0], %1;" :: "r"(a), "r"(cnt) : "memory");
}
// acquire at CLUSTER scope: orders subsequent remote DSMEM loads
__device__ __forceinline__ void mbar_wait_cl(unsigned a, unsigned par) {
    unsigned done;
    asm volatile(
        "{\n\t.reg .pred p;\n\t"
        "mbarrier.try_wait.parity.acquire.cluster.shared::cta.b64 p, [%1], %2;\n\t"
        "selp.b32 %0, 1, 0, p;\n\t}"
        : "=r"(done) : "r"(a), "r"(par) : "memory");
    if (!done) {
        asm volatile(
            "{\n\t.reg .pred P1;\n"
            "WAIT_%=:\n\t"
            "mbarrier.try_wait.parity.acquire.cluster.shared::cta.b64 P1, [%0], %1, 0x989680;\n\t"
            "@P1 bra DONE_%=;\n\t"
            "bra WAIT_%=;\n"
            "DONE_%=:\n\t}"
            :: "r"(a), "r"(par) : "memory");
    }
}
// remote arrive with explicit release.cluster semantics
__device__ __forceinline__ void mbar_arrive_remote(unsigned local_addr, int rank) {
    unsigned ra = mapa_(local_addr, rank);
    asm volatile("mbarrier.arrive.release.cluster.shared::cluster.b64 _, [%0];"
                 :: "r"(ra) : "memory");
}
// 16B DSMEM load (remote or local CTA of the cluster)
__device__ __forceinline__ void ld2c(ull& a, ull& b, unsigned addr) {
    asm volatile("ld.shared::cluster.v2.u64 {%0, %1}, [%2];"
                 : "=l"(a), "=l"(b) : "r"(addr));
}

// ======================================================================
// Encoder (PULL model): 16 clusters x 8 CTAs, 4 batch/cluster.
// Whh slice in registers (f32x2). Each CTA stores only its OWN 38-unit
// h chunk locally; consumers read all 8 chunks via ld.shared::cluster
// inside the GEMM (depth-2 pipelined). Sync = 8 remote mbarrier arrives.
// Trailing cluster_sync prevents exit-while-being-read (R5 ULF fix).
// ======================================================================
__global__ void __launch_bounds__(TENC, 1) __cluster_dims__(CLUSTER, 1, 1)
enc_kernel(const float* __restrict__ x,
           const float* __restrict__ Wih,
           const float* __restrict__ Whh,
           const float* __restrict__ bih,
           const float* __restrict__ bhh)
{
    __shared__ __align__(16) float2 hown[2][NB][KSEG2P];   // 1280 B (own chunk)
    __shared__ float2 part2[NB][KSPLIT][RG];                // 15360 B
    __shared__ float2 xst[2][NB][7];                        // 448 B
    __shared__ ull    wihs[HC][21];                         // gate Wih rows (f32x2)
    __shared__ ull    mbars[2];

    const int tid = threadIdx.x;
    unsigned rank;
    asm("mov.u32 %0, %%cluster_ctarank;" : "=r"(rank));
    const int bg = (blockIdx.x / CLUSTER) * NB;

    // ---- zero own h chunk (both buffers, incl. pad floats 38,39) ----
    {
        float* hf = (float*)hown;
        for (int i = tid; i < 2 * NB * KSEG2P * 2; i += TENC) hf[i] = 0.f;
    }
    // ---- gate Wih rows into SMEM (f32x2 packed) ----
    for (int i = tid; i < HC * 21; i += TENC) {
        int gi = i / 21, j = i % 21, g = j / 7, fp = j % 7;
        int u = (int)rank * HC + gi;
        float a = 0.f, b = 0.f;
        if (u < HID) {
            a = Wih[(g * HID + u) * FEAT + 2 * fp];
            if (2 * fp + 1 < FEAT) b = Wih[(g * HID + u) * FEAT + 2 * fp + 1];
        }
        wihs[gi][j] = pk2(a, b);
    }

    // ---- gemm role: Whh slice into registers ----
    const int ks = tid / RG;          // 0..7 : source rank chunk
    const int rg = tid % RG;          // 0..59
    const int row0 = rg * 2;
    ull w0[KSEG2P], w1[KSEG2P];
    {
        int g0 = row0 / ROWP, i0 = row0 % ROWP, u0 = (int)rank * HC + i0;
        bool ok0 = (i0 < HC) && (u0 < HID);
        int g1 = (row0 + 1) / ROWP, i1 = (row0 + 1) % ROWP, u1 = (int)rank * HC + i1;
        bool ok1 = (i1 < HC) && (u1 < HID);
#pragma unroll
        for (int kp = 0; kp < KSEG2P; kp++) {
            int j0 = kp * 2, j1 = kp * 2 + 1;              // float index in chunk
            int kg0 = ks * HC + j0, kg1 = ks * HC + j1;    // global k
            float a0 = (ok0 && j0 < HC && kg0 < HID) ? Whh[(g0 * HID + u0) * HID + kg0] : 0.f;
            float b0 = (ok0 && j1 < HC && kg1 < HID) ? Whh[(g0 * HID + u0) * HID + kg1] : 0.f;
            float a1 = (ok1 && j0 < HC && kg0 < HID) ? Whh[(g1 * HID + u1) * HID + kg0] : 0.f;
            float b1 = (ok1 && j1 < HC && kg1 < HID) ? Whh[(g1 * HID + u1) * HID + kg1] : 0.f;
            w0[kp] = pk2(a0, b0);
            w1[kp] = pk2(a1, b1);
        }
    }

    // ---- gate role (tid < 152) ----
    const int gb = tid / HC;
    const int gi_ = tid % HC;
    const int u_g = (int)rank * HC + gi_;
    const bool gate_ok = (tid < NB * HC) && (u_g < HID);
    float brz0 = 0.f, brz1 = 0.f, bin_ = 0.f, bhn_ = 0.f, h_keep = 0.f;
    if (gate_ok) {
        brz0 = bih[u_g]           + bhh[u_g];
        brz1 = bih[HID + u_g]     + bhh[HID + u_g];
        bin_ = bih[2 * HID + u_g];
        bhn_ = bhh[2 * HID + u_g];
    }

    // ---- x staging role: threads 152..179 ----
    const int xb_ = (tid - NB * HC) / 7;
    const int xfp = (tid - NB * HC) % 7;
    const bool xok = (tid >= NB * HC) && (tid < NB * HC + NB * 7);
    if (xok) {
        const float* xp = x + ((long)(bg + xb_) * T_STEPS) * FEAT + 2 * xfp;
        float a = xp[0];
        float b = (2 * xfp + 1 < FEAT) ? xp[1] : 0.f;
        xst[0][xb_][xfp] = make_float2(a, b);
    }

    // ---- barriers: count 8 (one arrive from each CTA) ----
    const unsigned barb = smem_u32(mbars);
    const unsigned hbase = smem_u32(hown);
    if (tid == 0) {
        mbar_init(barb, CLUSTER);
        mbar_init(barb + 8, CLUSTER);
    }
    __syncthreads();
    cluster_sync_();   // all CTAs: zeroed h + barriers visible cluster-wide

    // remote base for my source chunk (CTA `ks`), parity offset added per step
    const unsigned rchunk = mapa_(hbase, ks);

    int par0 = 0, par1 = 0;

    for (int t = 0; t < T_STEPS; t++) {
        const int p = t & 1;

        if (t) {
            const unsigned bw = barb + (unsigned)(t & 1) * 8u;
            mbar_wait_cl(bw, (t & 1) ? (unsigned)par1 : (unsigned)par0);
            if (t & 1) par1 ^= 1; else par0 ^= 1;
        }

        // x prefetch for t+1 (hides under GEMM)
        if (xok && t + 1 < T_STEPS) {
            const float* xp = x + ((long)(bg + xb_) * T_STEPS + (t + 1)) * FEAT + 2 * xfp;
            float a = __ldg(xp);
            float b = (2 * xfp + 1 < FEAT) ? __ldg(xp + 1) : 0.f;
            xst[p ^ 1][xb_][xfp] = make_float2(a, b);
        }

        // ---- GEMM: read chunk `ks` from CTA `ks` via DSMEM, depth-2 pipeline ----
        {
            const unsigned rb = rchunk + (unsigned)p * PSTRIDE;
            ull a00 = 0, a01 = 0, a10 = 0, a11 = 0;
            ull a20 = 0, a21 = 0, a30 = 0, a31 = 0;
            ull hv[2][8];
#define LOADU(buf, uu) do { \
            ld2c(hv[buf][0], hv[buf][1], rb + 0*BSTRIDE + (uu)*16u); \
            ld2c(hv[buf][2], hv[buf][3], rb + 1*BSTRIDE + (uu)*16u); \
            ld2c(hv[buf][4], hv[buf][5], rb + 2*BSTRIDE + (uu)*16u); \
            ld2c(hv[buf][6], hv[buf][7], rb + 3*BSTRIDE + (uu)*16u); } while (0)
            LOADU(0, 0);
            LOADU(1, 1);
#pragma unroll
            for (int uu = 0; uu < KSEG2P / 2; uu++) {
                const int bs = uu & 1;
                fma2(a00, w0[2*uu],   hv[bs][0]); fma2(a01, w1[2*uu],   hv[bs][0]);
                fma2(a00, w0[2*uu+1], hv[bs][1]); fma2(a01, w1[2*uu+1], hv[bs][1]);
                fma2(a10, w0[2*uu],   hv[bs][2]); fma2(a11, w1[2*uu],   hv[bs][2]);
                fma2(a10, w0[2*uu+1], hv[bs][3]); fma2(a11, w1[2*uu+1], hv[bs][3]);
                fma2(a20, w0[2*uu],   hv[bs][4]); fma2(a21, w1[2*uu],   hv[bs][4]);
                fma2(a20, w0[2*uu+1], hv[bs][5]); fma2(a21, w1[2*uu+1], hv[bs][5]);
                fma2(a30, w0[2*uu],   hv[bs][6]); fma2(a31, w1[2*uu],   hv[bs][6]);
                fma2(a30, w0[2*uu+1], hv[bs][7]); fma2(a31, w1[2*uu+1], hv[bs][7]);
                if (uu + 2 < KSEG2P / 2) LOADU(bs, uu + 2);
            }
#undef LOADU
            part2[0][ks][rg] = make_float2(upks(a00), upks(a01));
            part2[1][ks][rg] = make_float2(upks(a10), upks(a11));
            part2[2][ks][rg] = make_float2(upks(a20), upks(a21));
            part2[3][ks][rg] = make_float2(upks(a30), upks(a31));
        }

        __syncthreads();

        if (gate_ok) {
            const float* pf = (const float*)part2;
            float s0 = 0.f, s1 = 0.f, s2 = 0.f;
#pragma unroll
            for (int q = 0; q < KSPLIT; q++) {
                const int base = (gb * KSPLIT + q) * R3;
                s0 += pf[base + gi_];
                s1 += pf[base + ROWP + gi_];
                s2 += pf[base + 2 * ROWP + gi_];
            }
            // input-gate dots (weights from SMEM)
            ull d0 = 0, d1 = 0, d2 = 0;
            const ull* xq = (const ull*)&xst[p][gb][0];
#pragma unroll
            for (int fp = 0; fp < 7; fp++) {
                ull xv = xq[fp];
                fma2(d0, wihs[gi_][fp],      xv);
                fma2(d1, wihs[gi_][7 + fp],  xv);
                fma2(d2, wihs[gi_][14 + fp], xv);
            }
            const float r = sig_f(upks(d0) + s0 + brz0);
            const float z = sig_f(upks(d1) + s1 + brz1);
            const float n = tanh_f(upks(d2) + bin_ + r * (s2 + bhn_));
            const float hn = (1.f - z) * n + z * h_keep;
            h_keep = hn;
            // write own chunk element (float view of hown)
            ((float*)hown)[(((p ^ 1) * NB + gb) * KSEG2P) * 2 + gi_] = hn;
        }

        // gate warps (+ riders) sync, then 8 remote arrives publish the chunk
        if (tid < 160) {
            asm volatile("bar.sync 1, 160;" ::: "memory");
            if (tid < CLUSTER && t + 1 < T_STEPS) {
                const unsigned bn = barb + (unsigned)((t + 1) & 1) * 8u;
                mbar_arrive_remote(bn, tid);
            }
        }
        // non-gate warps fall through to next mbar_wait (WAR on part2 is
        // protected transitively: wait passes only after all CTAs' gates done)
    }

    if (gate_ok) g_hlast[(bg + gb) * HID + u_g] = h_keep;

    // CRITICAL: no CTA may exit while siblings may still read its SMEM chunk
    cluster_sync_();
}

// ======================================================================
// fc + relu
// ======================================================================
__global__ void __launch_bounds__(128) fc_kernel(
    const float* __restrict__ fcW, const float* __restrict__ fcb,
    float* __restrict__ dout, int write_emb)
{
    __shared__ float hs[HID];
    const int b = blockIdx.x;
    const int tid = threadIdx.x;
    for (int k = tid; k < HID; k += 128) hs[k] = g_hlast[b * HID + k];
    __syncthreads();
    for (int j = tid; j < HID; j += 128) {
        float a = fcb[j];
        const float* w = fcW + j * HID;
#pragma unroll 4
        for (int k = 0; k < HID; k++) a = fmaf(w[k], hs[k], a);
        a = fmaxf(a, 0.f);
        g_emb[b * HID + j] = a;
        if (write_emb) dout[OUT_EMB_OFF + b * HID + j] = a;
    }
}

// ======================================================================
// Decoder: one warp per batch element, h broadcast via shfl.
// ======================================================================
__global__ void __launch_bounds__(32) dec_kernel(
    const float* __restrict__ dWih, const float* __restrict__ dWhh,
    const float* __restrict__ dbih, const float* __restrict__ dbhh,
    float* __restrict__ out)
{
    const int b = blockIdx.x;
    const int lane = threadIdx.x;

    float wr[FEAT], wz[FEAT], wn[FEAT];
    float gr0 = 0.f, gz0 = 0.f, gn0 = 0.f, bhn = 0.f, h = 0.f;

    if (lane < FEAT) {
        gr0 = dbih[lane]            + dbhh[lane];
        gz0 = dbih[FEAT + lane]     + dbhh[FEAT + lane];
        gn0 = dbih[2 * FEAT + lane];
        bhn = dbhh[2 * FEAT + lane];
        const float* e  = g_emb + b * HID;
        const float* w0 = dWih + lane * HID;
        const float* w1 = dWih + (FEAT + lane) * HID;
        const float* w2 = dWih + (2 * FEAT + lane) * HID;
#pragma unroll 4
        for (int k = 0; k < HID; k++) {
            float ev = e[k];
            gr0 = fmaf(w0[k], ev, gr0);
            gz0 = fmaf(w1[k], ev, gz0);
            gn0 = fmaf(w2[k], ev, gn0);
        }
#pragma unroll
        for (int k = 0; k < FEAT; k++) {
            wr[k] = dWhh[lane * FEAT + k];
            wz[k] = dWhh[(FEAT + lane) * FEAT + k];
            wn[k] = dWhh[(2 * FEAT + lane) * FEAT + k];
        }
    }

    float* ob = out + (long)b * T_STEPS * FEAT;
    for (int t = 0; t < T_STEPS; t++) {
        float sr = 0.f, sz = 0.f, sn = 0.f;
#pragma unroll
        for (int k = 0; k < FEAT; k++) {
            float hk = __shfl_sync(0xffffffffu, h, k);
            sr = fmaf(wr[k], hk, sr);
            sz = fmaf(wz[k], hk, sz);
            sn = fmaf(wn[k], hk, sn);
        }
        if (lane < FEAT) {
            float r = sig_f(gr0 + sr);
            float z = sig_f(gz0 + sz);
            float n = tanh_f(gn0 + r * (sn + bhn));
            h = (1.f - z) * n + z * h;
            ob[t * FEAT + lane] = h;
        }
    }
}

// ======================================================================
// launch
// ======================================================================
extern "C" void kernel_launch(void* const* d_in, const int* in_sizes, int n_in,
                              void* d_out, int out_size)
{
    const float* x        = (const float*)d_in[0];
    const float* enc_Wih  = (const float*)d_in[1];
    const float* enc_Whh  = (const float*)d_in[2];
    const float* enc_bih  = (const float*)d_in[3];
    const float* enc_bhh  = (const float*)d_in[4];
    const float* fc_W     = (const float*)d_in[5];
    const float* fc_b     = (const float*)d_in[6];
    const float* dec_Wih  = (const float*)d_in[7];
    const float* dec_Whh  = (const float*)d_in[8];
    const float* dec_bih  = (const float*)d_in[9];
    const float* dec_bhh  = (const float*)d_in[10];
    float* out = (float*)d_out;

    const int write_emb = (out_size >= OUT_MAIN + BATCH * HID) ? 1 : 0;

    enc_kernel<<<(BATCH / NB) * CLUSTER, TENC>>>(
        x, enc_Wih, enc_Whh, enc_bih, enc_bhh);
    fc_kernel<<<BATCH, 128>>>(fc_W, fc_b, out, write_emb);
    dec_kernel<<<BATCH, 32>>>(dec_Wih, dec_Whh, dec_bih, dec_bhh, out);
}

// round 8
// speedup vs baseline: 1.3134x; 1.3134x over previous
#include <cuda_runtime.h>
#include <cstdint>

typedef unsigned long long ull;

// ---------------- problem constants ----------------
#define T_STEPS 2048
#define BATCH   64
#define FEAT    13
#define HID     300
#define OUT_MAIN (BATCH*T_STEPS*FEAT)
#define OUT_EMB_OFF OUT_MAIN

// ---------------- encoder config ----------------
#define CLUSTER 8
#define NGROUP  2               // pipelined batch groups
#define NBG     2               // batch per group
#define NB      (NGROUP*NBG)    // 4 batch per cluster
#define TENC    576             // 480 gemm + 96 gate threads
#define NGEMM   480
#define HC      38              // hidden units per CTA (8*38 = 304)
#define ROWP    40              // padded rows per gate
#define R3      120
#define KSPLIT  8
#define KSEG2   19              // k-pairs per split (38 floats)
#define RG      60              // row-pairs
#define KFLOAT  304             // padded h vector length

// named barriers: 1 = partials A ready, 2 = partials B ready, 3 = gate-internal
#define BAR_PART_A 1
#define BAR_PART_B 2
#define BAR_GATES  3

__device__ float g_hlast[BATCH*HID];
__device__ float g_emb[BATCH*HID];

// ---------------- helpers ----------------
__device__ __forceinline__ float sig_f(float x) {
    return __fdividef(1.f, 1.f + __expf(-x));
}
__device__ __forceinline__ float tanh_f(float x) {
    return 1.f - __fdividef(2.f, __expf(2.f * x) + 1.f);
}
__device__ __forceinline__ unsigned smem_u32(const void* p) {
    unsigned a;
    asm("{ .reg .u64 t; cvta.to.shared.u64 t, %1; cvt.u32.u64 %0, t; }"
        : "=r"(a) : "l"(p));
    return a;
}
__device__ __forceinline__ void cluster_sync_() {
    asm volatile("barrier.cluster.arrive.aligned;" ::: "memory");
    asm volatile("barrier.cluster.wait.aligned;" ::: "memory");
}
__device__ __forceinline__ ull pk2(float lo, float hi) {
    ull r;
    asm("mov.b64 %0, {%1, %2};" : "=l"(r) : "f"(lo), "f"(hi));
    return r;
}
__device__ __forceinline__ void fma2(ull& d, ull a, ull b) {
    asm("fma.rn.f32x2 %0, %1, %2, %0;" : "+l"(d) : "l"(a), "l"(b));
}
__device__ __forceinline__ float upks(ull v) {
    float lo, hi;
    asm("mov.b64 {%0, %1}, %2;" : "=f"(lo), "=f"(hi) : "l"(v));
    return lo + hi;
}
__device__ __forceinline__ unsigned mapa_(unsigned a, int rank) {
    unsigned r;
    asm("mapa.shared::cluster.u32 %0, %1, %2;" : "=r"(r) : "r"(a), "r"(rank));
    return r;
}
__device__ __forceinline__ void mbar_init(unsigned a, unsigned cnt) {
    asm volatile("mbarrier.init.shared.b64 [%0], %1;" :: "r"(a), "r"(cnt) : "memory");
}
__device__ __forceinline__ void mbar_wait_cl(unsigned a, unsigned par) {
    unsigned done;
    asm volatile(
        "{\n\t.reg .pred p;\n\t"
        "mbarrier.try_wait.parity.acquire.cluster.shared::cta.b64 p, [%1], %2;\n\t"
        "selp.b32 %0, 1, 0, p;\n\t}"
        : "=r"(done) : "r"(a), "r"(par) : "memory");
    if (!done) {
        asm volatile(
            "{\n\t.reg .pred P1;\n"
            "WAIT_%=:\n\t"
            "mbarrier.try_wait.parity.acquire.cluster.shared::cta.b64 P1, [%0], %1, 0x989680;\n\t"
            "@P1 bra DONE_%=;\n\t"
            "bra WAIT_%=;\n"
            "DONE_%=:\n\t}"
            :: "r"(a), "r"(par) : "memory");
    }
}
__device__ __forceinline__ void mbar_arrive_remote(unsigned local_addr, int rank) {
    unsigned ra = mapa_(local_addr, rank);
    asm volatile("mbarrier.arrive.release.cluster.shared::cluster.b64 _, [%0];"
                 :: "r"(ra) : "memory");
}
__device__ __forceinline__ void st_remote_f32(unsigned raddr, float v) {
    asm volatile("st.shared::cluster.f32 [%0], %1;" :: "r"(raddr), "f"(v) : "memory");
}
__device__ __forceinline__ void fence_cluster_() {
    asm volatile("fence.acq_rel.cluster;" ::: "memory");
}
__device__ __forceinline__ void bar_arrive(int id, int cnt) {
    asm volatile("bar.arrive %0, %1;" :: "r"(id), "r"(cnt) : "memory");
}
__device__ __forceinline__ void bar_sync(int id, int cnt) {
    asm volatile("bar.sync %0, %1;" :: "r"(id), "r"(cnt) : "memory");
}

// ======================================================================
// Encoder: warp-specialized two-group pipeline. 16 clusters x 8 CTAs.
// GEMM warps (480 thr): per step GEMM_A then GEMM_B (weights in regs).
// Gate warps (96 thr): reduce partials, gates, DSMEM h push, mbar arrive.
// Group A's comm round-trip hides under group B's GEMM and vice versa.
// ======================================================================
__global__ void __launch_bounds__(TENC, 1) __cluster_dims__(CLUSTER, 1, 1)
enc_kernel(const float* __restrict__ x,
           const float* __restrict__ Wih,
           const float* __restrict__ Whh,
           const float* __restrict__ bih,
           const float* __restrict__ bhh)
{
    __shared__ __align__(16) float  hbuf[NGROUP][2][NBG][KFLOAT];     // 9728 B
    __shared__ __align__(16) float2 part[NGROUP][2][NBG][KSPLIT][RG]; // 30720 B
    __shared__ __align__(16) float  xst[NGROUP][2][NBG][14];          // 896 B
    __shared__ ull fullbar[NGROUP][2];

    const int tid = threadIdx.x;
    unsigned rank;
    asm("mov.u32 %0, %%cluster_ctarank;" : "=r"(rank));
    const int bg = (blockIdx.x / CLUSTER) * NB;

    // ---- zero h buffers + x staging ----
    {
        float* hf = (float*)hbuf;
        for (int i = tid; i < NGROUP * 2 * NBG * KFLOAT; i += TENC) hf[i] = 0.f;
        float* xf = (float*)xst;
        for (int i = tid; i < NGROUP * 2 * NBG * 14; i += TENC) xf[i] = 0.f;
    }

    const unsigned barb  = smem_u32(&fullbar[0][0]);
    const unsigned hbase = smem_u32(hbuf);
    if (tid == 0) {
        mbar_init(barb,      CLUSTER);   // A buf0
        mbar_init(barb + 8,  CLUSTER);   // A buf1
        mbar_init(barb + 16, CLUSTER);   // B buf0
        mbar_init(barb + 24, CLUSTER);   // B buf1
    }
    __syncthreads();

    if (tid < NGEMM) {
        // =================== GEMM role ===================
        const int ks = tid / RG;          // 0..7
        const int rg = tid % RG;          // 0..59
        const int row0 = rg * 2;
        ull w0[KSEG2], w1[KSEG2];
        {
            int ga = row0 / ROWP, ia = row0 % ROWP, ua = (int)rank * HC + ia;
            bool oka = (ia < HC) && (ua < HID);
            int gb2 = (row0 + 1) / ROWP, ib = (row0 + 1) % ROWP, ub = (int)rank * HC + ib;
            bool okb = (ib < HC) && (ub < HID);
#pragma unroll
            for (int kp = 0; kp < KSEG2; kp++) {
                int k0 = ks * HC + 2 * kp, k1 = k0 + 1;
                float a0 = (oka && k0 < HID) ? Whh[(ga * HID + ua) * HID + k0] : 0.f;
                float b0 = (oka && k1 < HID) ? Whh[(ga * HID + ua) * HID + k1] : 0.f;
                float a1 = (okb && k0 < HID) ? Whh[(gb2 * HID + ub) * HID + k0] : 0.f;
                float b1 = (okb && k1 < HID) ? Whh[(gb2 * HID + ub) * HID + k1] : 0.f;
                w0[kp] = pk2(a0, b0);
                w1[kp] = pk2(a1, b1);
            }
        }
        __syncthreads();
        cluster_sync_();

        for (int t = 0; t < T_STEPS; t++) {
            const int p = t & 1;
            const unsigned par = (unsigned)(((t - 1) >> 1) & 1);

            // ---- group A ----
            if (t) mbar_wait_cl(barb + (unsigned)p * 8u, par);
            {
                const float* hb = &hbuf[0][p][0][0];
                const ull* hp0 = (const ull*)(hb + ks * HC);
                const ull* hp1 = (const ull*)(hb + KFLOAT + ks * HC);
                ull a00 = 0, a01 = 0, a10 = 0, a11 = 0;
#pragma unroll
                for (int kp = 0; kp < KSEG2; kp++) {
                    ull h0 = hp0[kp], h1 = hp1[kp];
                    fma2(a00, w0[kp], h0); fma2(a01, w1[kp], h0);
                    fma2(a10, w0[kp], h1); fma2(a11, w1[kp], h1);
                }
                part[0][p][0][ks][rg] = make_float2(upks(a00), upks(a01));
                part[0][p][1][ks][rg] = make_float2(upks(a10), upks(a11));
            }
            bar_arrive(BAR_PART_A, TENC);

            // ---- group B ----
            if (t) mbar_wait_cl(barb + (unsigned)(2 + p) * 8u, par);
            {
                const float* hb = &hbuf[1][p][0][0];
                const ull* hp0 = (const ull*)(hb + ks * HC);
                const ull* hp1 = (const ull*)(hb + KFLOAT + ks * HC);
                ull a00 = 0, a01 = 0, a10 = 0, a11 = 0;
#pragma unroll
                for (int kp = 0; kp < KSEG2; kp++) {
                    ull h0 = hp0[kp], h1 = hp1[kp];
                    fma2(a00, w0[kp], h0); fma2(a01, w1[kp], h0);
                    fma2(a10, w0[kp], h1); fma2(a11, w1[kp], h1);
                }
                part[1][p][0][ks][rg] = make_float2(upks(a00), upks(a01));
                part[1][p][1][ks][rg] = make_float2(upks(a10), upks(a11));
            }
            bar_arrive(BAR_PART_B, TENC);
        }
    } else {
        // =================== gate role (96 threads) ===================
        const int gt = tid - NGEMM;
        const int gb2 = gt / HC;          // batch within group (0/1)
        const int gi_ = gt % HC;
        const int u_g = (int)rank * HC + gi_;
        const bool active = (gt < NBG * HC) && (u_g < HID);

        ull wihr[3][7];
        float brz0 = 0.f, brz1 = 0.f, bin_ = 0.f, bhn_ = 0.f;
        float h_keep[NGROUP] = {0.f, 0.f};
        if (active) {
#pragma unroll
            for (int g = 0; g < 3; g++)
#pragma unroll
                for (int fp = 0; fp < 7; fp++) {
                    float a = Wih[(g * HID + u_g) * FEAT + 2 * fp];
                    float b = (2 * fp + 1 < FEAT) ? Wih[(g * HID + u_g) * FEAT + 2 * fp + 1] : 0.f;
                    wihr[g][fp] = pk2(a, b);
                }
            brz0 = bih[u_g]           + bhh[u_g];
            brz1 = bih[HID + u_g]     + bhh[HID + u_g];
            bin_ = bih[2 * HID + u_g];
            bhn_ = bhh[2 * HID + u_g];
        }
        // remote hbuf bases (one per destination CTA)
        unsigned rbase[CLUSTER];
#pragma unroll
        for (int c = 0; c < CLUSTER; c++) rbase[c] = mapa_(hbase, c);

        // prime x(0) for both groups
        if (gt < NGROUP * NBG * FEAT) {
            int g = gt / (NBG * FEAT), r = gt % (NBG * FEAT);
            int b = r / FEAT, f = r % FEAT;
            xst[g][0][b][f] = x[((long)(bg + g * NBG + b) * T_STEPS) * FEAT + f];
        }
        __syncthreads();
        cluster_sync_();

        for (int t = 0; t < T_STEPS; t++) {
            const int p = t & 1;
            const int buf = p ^ 1;

#pragma unroll
            for (int g = 0; g < NGROUP; g++) {
                bar_sync(g == 0 ? BAR_PART_A : BAR_PART_B, TENC);

                // x prefetch for t+1 (this group's batches)
                if (gt < NBG * FEAT && t + 1 < T_STEPS) {
                    int b = gt / FEAT, f = gt % FEAT;
                    xst[g][buf][b][f] =
                        __ldg(&x[((long)(bg + g * NBG + b) * T_STEPS + t + 1) * FEAT + f]);
                }

                if (active) {
                    const float* pf = (const float*)&part[g][p][gb2][0][0];
                    float s0 = 0.f, s1 = 0.f, s2 = 0.f;
#pragma unroll
                    for (int q = 0; q < KSPLIT; q++) {
                        const int base = q * R3;
                        s0 += pf[base + gi_];
                        s1 += pf[base + ROWP + gi_];
                        s2 += pf[base + 2 * ROWP + gi_];
                    }
                    ull d0 = 0, d1 = 0, d2 = 0;
                    const ull* xq = (const ull*)&xst[g][p][gb2][0];
#pragma unroll
                    for (int fp = 0; fp < 7; fp++) {
                        ull xv = xq[fp];
                        fma2(d0, wihr[0][fp], xv);
                        fma2(d1, wihr[1][fp], xv);
                        fma2(d2, wihr[2][fp], xv);
                    }
                    const float r = sig_f(upks(d0) + s0 + brz0);
                    const float z = sig_f(upks(d1) + s1 + brz1);
                    const float n = tanh_f(upks(d2) + bin_ + r * (s2 + bhn_));
                    const float hn = (1.f - z) * n + z * h_keep[g];
                    h_keep[g] = hn;

                    if (t + 1 < T_STEPS) {
                        const unsigned off =
                            (unsigned)(((g * 2 + buf) * NBG + gb2) * KFLOAT + u_g) * 4u;
#pragma unroll
                        for (int c = 0; c < CLUSTER; c++)
                            st_remote_f32(rbase[c] + off, hn);
                    }
                }
                bar_sync(BAR_GATES, TENC - NGEMM);
                if (t + 1 < T_STEPS && gt < CLUSTER) {
                    fence_cluster_();
                    mbar_arrive_remote(barb + (unsigned)(g * 2 + buf) * 8u, gt);
                }
            }
        }

        if (active) {
#pragma unroll
            for (int g = 0; g < NGROUP; g++)
                g_hlast[(bg + g * NBG + gb2) * HID + u_g] = h_keep[g];
        }
    }

    // no CTA may exit while siblings may still write/read its SMEM
    cluster_sync_();
}

// ======================================================================
// fc + relu
// ======================================================================
__global__ void __launch_bounds__(128) fc_kernel(
    const float* __restrict__ fcW, const float* __restrict__ fcb,
    float* __restrict__ dout, int write_emb)
{
    __shared__ float hs[HID];
    const int b = blockIdx.x;
    const int tid = threadIdx.x;
    for (int k = tid; k < HID; k += 128) hs[k] = g_hlast[b * HID + k];
    __syncthreads();
    for (int j = tid; j < HID; j += 128) {
        float a = fcb[j];
        const float* w = fcW + j * HID;
#pragma unroll 4
        for (int k = 0; k < HID; k++) a = fmaf(w[k], hs[k], a);
        a = fmaxf(a, 0.f);
        g_emb[b * HID + j] = a;
        if (write_emb) dout[OUT_EMB_OFF + b * HID + j] = a;
    }
}

// ======================================================================
// Decoder: one warp per batch element, h broadcast via shfl.
// ======================================================================
__global__ void __launch_bounds__(32) dec_kernel(
    const float* __restrict__ dWih, const float* __restrict__ dWhh,
    const float* __restrict__ dbih, const float* __restrict__ dbhh,
    float* __restrict__ out)
{
    const int b = blockIdx.x;
    const int lane = threadIdx.x;

    float wr[FEAT], wz[FEAT], wn[FEAT];
    float gr0 = 0.f, gz0 = 0.f, gn0 = 0.f, bhn = 0.f, h = 0.f;

    if (lane < FEAT) {
        gr0 = dbih[lane]            + dbhh[lane];
        gz0 = dbih[FEAT + lane]     + dbhh[FEAT + lane];
        gn0 = dbih[2 * FEAT + lane];
        bhn = dbhh[2 * FEAT + lane];
        const float* e  = g_emb + b * HID;
        const float* w0 = dWih + lane * HID;
        const float* w1 = dWih + (FEAT + lane) * HID;
        const float* w2 = dWih + (2 * FEAT + lane) * HID;
#pragma unroll 4
        for (int k = 0; k < HID; k++) {
            float ev = e[k];
            gr0 = fmaf(w0[k], ev, gr0);
            gz0 = fmaf(w1[k], ev, gz0);
            gn0 = fmaf(w2[k], ev, gn0);
        }
#pragma unroll
        for (int k = 0; k < FEAT; k++) {
            wr[k] = dWhh[lane * FEAT + k];
            wz[k] = dWhh[(FEAT + lane) * FEAT + k];
            wn[k] = dWhh[(2 * FEAT + lane) * FEAT + k];
        }
    }

    float* ob = out + (long)b * T_STEPS * FEAT;
    for (int t = 0; t < T_STEPS; t++) {
        float sr = 0.f, sz = 0.f, sn = 0.f;
#pragma unroll
        for (int k = 0; k < FEAT; k++) {
            float hk = __shfl_sync(0xffffffffu, h, k);
            sr = fmaf(wr[k], hk, sr);
            sz = fmaf(wz[k], hk, sz);
            sn = fmaf(wn[k], hk, sn);
        }
        if (lane < FEAT) {
            float r = sig_f(gr0 + sr);
            float z = sig_f(gz0 + sz);
            float n = tanh_f(gn0 + r * (sn + bhn));
            h = (1.f - z) * n + z * h;
            ob[t * FEAT + lane] = h;
        }
    }
}

// ======================================================================
// launch
// ======================================================================
extern "C" void kernel_launch(void* const* d_in, const int* in_sizes, int n_in,
                              void* d_out, int out_size)
{
    const float* x        = (const float*)d_in[0];
    const float* enc_Wih  = (const float*)d_in[1];
    const float* enc_Whh  = (const float*)d_in[2];
    const float* enc_bih  = (const float*)d_in[3];
    const float* enc_bhh  = (const float*)d_in[4];
    const float* fc_W     = (const float*)d_in[5];
    const float* fc_b     = (const float*)d_in[6];
    const float* dec_Wih  = (const float*)d_in[7];
    const float* dec_Whh  = (const float*)d_in[8];
    const float* dec_bih  = (const float*)d_in[9];
    const float* dec_bhh  = (const float*)d_in[10];
    float* out = (float*)d_out;

    const int write_emb = (out_size >= OUT_MAIN + BATCH * HID) ? 1 : 0;

    enc_kernel<<<(BATCH / NB) * CLUSTER, TENC>>>(
        x, enc_Wih, enc_Whh, enc_bih, enc_bhh);
    fc_kernel<<<BATCH, 128>>>(fc_W, fc_b, out, write_emb);
    dec_kernel<<<BATCH, 32>>>(dec_Wih, dec_Whh, dec_bih, dec_bhh, out);
}